// round 1
// baseline (speedup 1.0000x reference)
#include <cuda_runtime.h>
#include <math.h>

#define NLAYER 6
#define H 512
#define NH 8
#define HD 64
#define FF 2048
#define VOCAB 50304
#define BATCH 2
#define S 1024
#define BS (BATCH*S)
#define ROT 16
#define ATT_SCALE 0.125f
#define LN_EPS 1e-5f

// ---------------- scratch (device globals; no allocation in kernel_launch) ----------------
__device__ float g_h[BS*H];                       // residual stream
__device__ float g_x[BS*H];                       // layernorm output
__device__ float g_qkv[BS*3*H];                   // qkv projection
__device__ float g_w[(size_t)BATCH*NH*S*S];       // normalized strict-causal weights (64MB)
__device__ float g_A[(size_t)BATCH*NH*S*HD];      // scan state
__device__ float g_attn[BS*H];                    // scan output in (b,s,h*d) layout
__device__ float g_ff[(size_t)BS*FF];             // mlp intermediate

// ---------------- embedding ----------------
__global__ void embed_kernel(const int* __restrict__ ids, const float* __restrict__ table) {
    int idx = blockIdx.x * blockDim.x + threadIdx.x;   // over BS*H
    int row = idx / H, d = idx - row * H;
    g_h[idx] = table[(size_t)ids[row] * H + d];
}

// ---------------- layernorm (block per row) ----------------
__global__ void ln_kernel(const float* __restrict__ in, float* __restrict__ out,
                          const float* __restrict__ gg, const float* __restrict__ bb) {
    int row = blockIdx.x;
    const float* x = in + (size_t)row * H;
    float s = 0.f, s2 = 0.f;
    for (int d = threadIdx.x; d < H; d += blockDim.x) { float v = x[d]; s += v; s2 += v * v; }
    __shared__ float r1[4], r2[4];
    int lane = threadIdx.x & 31, wid = threadIdx.x >> 5;
    #pragma unroll
    for (int o = 16; o; o >>= 1) {
        s  += __shfl_xor_sync(0xffffffffu, s,  o);
        s2 += __shfl_xor_sync(0xffffffffu, s2, o);
    }
    if (lane == 0) { r1[wid] = s; r2[wid] = s2; }
    __syncthreads();
    s  = r1[0] + r1[1] + r1[2] + r1[3];
    s2 = r2[0] + r2[1] + r2[2] + r2[3];
    float m   = s * (1.0f / H);
    float var = s2 * (1.0f / H) - m * m;
    float inv = rsqrtf(var + LN_EPS);
    for (int d = threadIdx.x; d < H; d += blockDim.x)
        out[(size_t)row * H + d] = (x[d] - m) * inv * gg[d] + bb[d];
}

// ---------------- SGEMM: C[M,N] = act(A[M,K] @ W[N,K]^T + bias) (+= if doacc) ----------------
// 128x128 tile, BK=8, 256 threads, 8x8 microtile.
__global__ void gemm128(const float* __restrict__ Ap, const float* __restrict__ Wp,
                        const float* __restrict__ bias, float* __restrict__ Cp,
                        int M, int N, int K, int dogelu, int doacc) {
    __shared__ float As[8][136];
    __shared__ float Bs[8][136];
    const int bm = blockIdx.y * 128, bn = blockIdx.x * 128;
    const int tid = threadIdx.x;
    const int tx = tid & 15, ty = tid >> 4;
    float acc[8][8];
    #pragma unroll
    for (int i = 0; i < 8; i++)
        #pragma unroll
        for (int j = 0; j < 8; j++) acc[i][j] = 0.f;

    const int lrow = tid >> 1;
    const int lk = (tid & 1) * 4;
    const float* Ag = Ap + (size_t)(bm + lrow) * K + lk;
    const float* Wg = Wp + (size_t)(bn + lrow) * K + lk;

    for (int k0 = 0; k0 < K; k0 += 8) {
        float4 a4 = *(const float4*)(Ag + k0);
        float4 b4 = *(const float4*)(Wg + k0);
        As[lk + 0][lrow] = a4.x; As[lk + 1][lrow] = a4.y;
        As[lk + 2][lrow] = a4.z; As[lk + 3][lrow] = a4.w;
        Bs[lk + 0][lrow] = b4.x; Bs[lk + 1][lrow] = b4.y;
        Bs[lk + 2][lrow] = b4.z; Bs[lk + 3][lrow] = b4.w;
        __syncthreads();
        #pragma unroll
        for (int kk = 0; kk < 8; kk++) {
            float av[8], bv[8];
            *(float4*)(av)     = *(const float4*)&As[kk][ty * 8];
            *(float4*)(av + 4) = *(const float4*)&As[kk][ty * 8 + 4];
            *(float4*)(bv)     = *(const float4*)&Bs[kk][tx * 8];
            *(float4*)(bv + 4) = *(const float4*)&Bs[kk][tx * 8 + 4];
            #pragma unroll
            for (int i = 0; i < 8; i++)
                #pragma unroll
                for (int j = 0; j < 8; j++)
                    acc[i][j] += av[i] * bv[j];
        }
        __syncthreads();
    }

    #pragma unroll
    for (int i = 0; i < 8; i++) {
        int m = bm + ty * 8 + i;
        float* crow = Cp + (size_t)m * N + bn + tx * 8;
        #pragma unroll
        for (int jj = 0; jj < 2; jj++) {
            float4 v = make_float4(acc[i][jj*4+0], acc[i][jj*4+1], acc[i][jj*4+2], acc[i][jj*4+3]);
            if (bias) {
                float4 bb4 = *(const float4*)(bias + bn + tx * 8 + jj * 4);
                v.x += bb4.x; v.y += bb4.y; v.z += bb4.z; v.w += bb4.w;
            }
            if (dogelu) {
                v.x = 0.5f * v.x * (1.0f + erff(v.x * 0.70710678118654752f));
                v.y = 0.5f * v.y * (1.0f + erff(v.y * 0.70710678118654752f));
                v.z = 0.5f * v.z * (1.0f + erff(v.z * 0.70710678118654752f));
                v.w = 0.5f * v.w * (1.0f + erff(v.w * 0.70710678118654752f));
            }
            if (doacc) {
                float4 o4 = *(const float4*)(crow + jj * 4);
                v.x += o4.x; v.y += o4.y; v.z += o4.z; v.w += o4.w;
            }
            *(float4*)(crow + jj * 4) = v;
        }
    }
}

// ---------------- RoPE (in place on q,k sections of g_qkv) ----------------
__global__ void rope_kernel() {
    int idx = blockIdx.x * blockDim.x + threadIdx.x;   // BS * 2 * NH * 8
    int j   = idx & 7;
    int h   = (idx >> 3) & 7;
    int sec = (idx >> 6) & 1;     // 0 = q, 1 = k
    int row = idx >> 7;           // 0..BS-1
    int pos = row & (S - 1);
    float inv = powf(10000.0f, -(float)j * 0.125f);    // 10000^(-2j/ROT)
    float ang = (float)pos * inv;
    float c = cosf(ang), sn = sinf(ang);
    float* base = g_qkv + (size_t)row * 1536 + sec * 512 + h * 64;
    float x1 = base[j], x2 = base[j + 8];
    base[j]     = x1 * c - x2 * sn;
    base[j + 8] = x2 * c + x1 * sn;
}

// ---------------- scores + softmax + strict-causal renorm (block per (b,h,i) row) ----------
// Writes w~[i][s] = exp(score_s - mx) / (Z_{s<i} + 1e-8 * Z_{s<=i})  for s < i.
__global__ void scores_kernel() {
    int i = blockIdx.x, h = blockIdx.y, b = blockIdx.z;
    __shared__ float sc[S];
    __shared__ float qv[HD];
    __shared__ float redm[4], rz[4], rzs[4];
    int tid = threadIdx.x;          // 128
    int lane = tid & 31, wid = tid >> 5;

    const float* qrow = g_qkv + (size_t)(b * S + i) * 1536 + h * 64;
    if (tid < 64) qv[tid] = qrow[tid];
    __syncthreads();

    float mx = -1e30f;
    for (int s = wid; s <= i; s += 4) {
        const float* krow = g_qkv + (size_t)(b * S + s) * 1536 + 512 + h * 64;
        float d = qv[lane] * krow[lane] + qv[lane + 32] * krow[lane + 32];
        #pragma unroll
        for (int o = 16; o; o >>= 1) d += __shfl_xor_sync(0xffffffffu, d, o);
        d *= ATT_SCALE;
        if (lane == 0) sc[s] = d;
        mx = fmaxf(mx, d);
    }
    if (lane == 0) redm[wid] = mx;
    __syncthreads();
    mx = fmaxf(fmaxf(redm[0], redm[1]), fmaxf(redm[2], redm[3]));

    float z = 0.f, zs = 0.f;
    for (int s = tid; s <= i; s += 128) {
        float e = expf(sc[s] - mx);
        sc[s] = e;
        z += e;
        if (s < i) zs += e;
    }
    #pragma unroll
    for (int o = 16; o; o >>= 1) {
        z  += __shfl_xor_sync(0xffffffffu, z,  o);
        zs += __shfl_xor_sync(0xffffffffu, zs, o);
    }
    if (lane == 0) { rz[wid] = z; rzs[wid] = zs; }
    __syncthreads();
    z  = rz[0]  + rz[1]  + rz[2]  + rz[3];
    zs = rzs[0] + rzs[1] + rzs[2] + rzs[3];

    float invd = 1.0f / (zs + 1e-8f * z);
    float* wrow = g_w + ((size_t)(b * NH + h) * S + i) * S;
    for (int s = tid; s < i; s += 128) wrow[s] = sc[s] * invd;
}

// ---------------- KA scan: sequential unit-lower-triangular recurrence ----------------
// One block per (b,h). 512 threads = 8 workers x 64 dims.
__global__ void scan_kernel() {
    int bh = blockIdx.x;
    int b = bh >> 3, h = bh & 7;
    const float* wbase = g_w + (size_t)bh * S * S;
    float* Ab = g_A + (size_t)bh * S * HD;
    int j  = threadIdx.x & 63;
    int wk = threadIdx.x >> 6;
    __shared__ float red[8][64];

    // A_0 = v_0
    if (threadIdx.x < 64) {
        float v = g_qkv[(size_t)(b * S) * 1536 + 1024 + h * 64 + j];
        Ab[j] = v;
        g_attn[(size_t)(b * S) * H + h * 64 + j] = v;
    }
    __syncthreads();

    for (int i = 1; i < S; i++) {
        const float* wrow = wbase + (size_t)i * S;
        float acc = 0.f;
        int s = wk;
        for (; s + 24 < i; s += 32) {
            acc += wrow[s]      * Ab[s * 64 + j];
            acc += wrow[s + 8]  * Ab[(s + 8) * 64 + j];
            acc += wrow[s + 16] * Ab[(s + 16) * 64 + j];
            acc += wrow[s + 24] * Ab[(s + 24) * 64 + j];
        }
        for (; s < i; s += 8) acc += wrow[s] * Ab[s * 64 + j];
        red[wk][j] = acc;
        __syncthreads();
        if (wk == 0) {
            float r = red[0][j] + red[1][j] + red[2][j] + red[3][j]
                    + red[4][j] + red[5][j] + red[6][j] + red[7][j];
            Ab[i * 64 + j] = r;
            g_attn[(size_t)(b * S + i) * H + h * 64 + j] = r;
        }
        __syncthreads();
    }
}

// ---------------- launcher ----------------
extern "C" void kernel_launch(void* const* d_in, const int* in_sizes, int n_in,
                              void* d_out, int out_size) {
    const int*   ids     = (const int*)d_in[0];
    const float* embed   = (const float*)d_in[1];
    const float* qkv_w   = (const float*)d_in[2];
    const float* qkv_b   = (const float*)d_in[3];
    const float* dense_w = (const float*)d_in[4];
    const float* dense_b = (const float*)d_in[5];
    const float* fc1_w   = (const float*)d_in[6];
    const float* fc1_b   = (const float*)d_in[7];
    const float* fc2_w   = (const float*)d_in[8];
    const float* fc2_b   = (const float*)d_in[9];
    const float* ln_g    = (const float*)d_in[10];
    const float* ln_b    = (const float*)d_in[11];
    const float* fln_g   = (const float*)d_in[12];
    const float* fln_b   = (const float*)d_in[13];
    const float* out_w   = (const float*)d_in[14];
    float* out = (float*)d_out;

    float *h, *x, *qkv, *attn, *ff;
    cudaGetSymbolAddress((void**)&h,    g_h);
    cudaGetSymbolAddress((void**)&x,    g_x);
    cudaGetSymbolAddress((void**)&qkv,  g_qkv);
    cudaGetSymbolAddress((void**)&attn, g_attn);
    cudaGetSymbolAddress((void**)&ff,   g_ff);

    embed_kernel<<<(BS * H) / 256, 256>>>(ids, embed);

    for (int l = 0; l < NLAYER; l++) {
        ln_kernel<<<BS, 128>>>(h, x, ln_g + l * H, ln_b + l * H);

        // qkv: (2048x512) @ (1536x512)^T + b
        gemm128<<<dim3(1536 / 128, BS / 128), 256>>>(
            x, qkv_w + (size_t)l * 3 * H * H, qkv_b + (size_t)l * 3 * H,
            qkv, BS, 3 * H, H, 0, 0);

        rope_kernel<<<(BS * 2 * NH * 8) / 256, 256>>>();

        scores_kernel<<<dim3(S, NH, BATCH), 128>>>();

        scan_kernel<<<BATCH * NH, 512>>>();

        // dense: attn @ dense_w^T + b, accumulated into residual h
        gemm128<<<dim3(H / 128, BS / 128), 256>>>(
            attn, dense_w + (size_t)l * H * H, dense_b + (size_t)l * H,
            h, BS, H, H, 0, 1);

        // fc1 with exact GELU
        gemm128<<<dim3(FF / 128, BS / 128), 256>>>(
            x, fc1_w + (size_t)l * FF * H, fc1_b + (size_t)l * FF,
            ff, BS, FF, H, 1, 0);

        // fc2 accumulated into residual h
        gemm128<<<dim3(H / 128, BS / 128), 256>>>(
            ff, fc2_w + (size_t)l * H * FF, fc2_b + (size_t)l * H,
            h, BS, H, FF, 0, 1);
    }

    ln_kernel<<<BS, 128>>>(h, x, fln_g, fln_b);

    // logits: (2048x512) @ (50304x512)^T
    gemm128<<<dim3(VOCAB / 128, BS / 128), 256>>>(
        x, out_w, nullptr, out, BS, VOCAB, H, 0, 0);
}

// round 2
// speedup vs baseline: 2.7107x; 2.7107x over previous
#include <cuda_runtime.h>
#include <math.h>

#define NLAYER 6
#define H 512
#define NH 8
#define HD 64
#define FF 2048
#define VOCAB 50304
#define BATCH 2
#define S 1024
#define BS (BATCH*S)
#define ATT_SCALE 0.125f
#define LN_EPS 1e-5f

// ---------------- scratch (device globals; no allocation in kernel_launch) ----------------
__device__ float g_h[BS*H];                       // residual stream
__device__ float g_x[BS*H];                       // layernorm output
__device__ float g_qkv[BS*3*H];                   // qkv projection
__device__ float g_w[(size_t)BATCH*NH*S*S];       // normalized strict-causal weights (64MB)
__device__ float g_c[BATCH*NH*S];                 // scalar scan coefficients
__device__ float g_attn[BS*H];                    // attention out (b,s,h*d)
__device__ float g_ff[(size_t)BS*FF];             // mlp intermediate

// ---------------- embedding ----------------
__global__ void embed_kernel(const int* __restrict__ ids, const float* __restrict__ table) {
    int idx = blockIdx.x * blockDim.x + threadIdx.x;   // over BS*H
    int row = idx / H, d = idx - row * H;
    g_h[idx] = table[(size_t)ids[row] * H + d];
}

// ---------------- layernorm (block per row) ----------------
__global__ void ln_kernel(const float* __restrict__ in, float* __restrict__ out,
                          const float* __restrict__ gg, const float* __restrict__ bb) {
    int row = blockIdx.x;
    const float* x = in + (size_t)row * H;
    float s = 0.f, s2 = 0.f;
    for (int d = threadIdx.x; d < H; d += blockDim.x) { float v = x[d]; s += v; s2 += v * v; }
    __shared__ float r1[4], r2[4];
    int lane = threadIdx.x & 31, wid = threadIdx.x >> 5;
    #pragma unroll
    for (int o = 16; o; o >>= 1) {
        s  += __shfl_xor_sync(0xffffffffu, s,  o);
        s2 += __shfl_xor_sync(0xffffffffu, s2, o);
    }
    if (lane == 0) { r1[wid] = s; r2[wid] = s2; }
    __syncthreads();
    s  = r1[0] + r1[1] + r1[2] + r1[3];
    s2 = r2[0] + r2[1] + r2[2] + r2[3];
    float m   = s * (1.0f / H);
    float var = s2 * (1.0f / H) - m * m;
    float inv = rsqrtf(var + LN_EPS);
    for (int d = threadIdx.x; d < H; d += blockDim.x)
        out[(size_t)row * H + d] = (x[d] - m) * inv * gg[d] + bb[d];
}

// ---------------- packed f32x2 helpers (sm_103a) ----------------
__device__ __forceinline__ void fma2(unsigned long long &d, unsigned long long a, unsigned long long b) {
    asm("fma.rn.f32x2 %0, %1, %2, %0;" : "+l"(d) : "l"(a), "l"(b));
}
__device__ __forceinline__ unsigned long long pack2(float x) {
    unsigned long long r;
    asm("mov.b64 %0, {%1, %1};" : "=l"(r) : "f"(x));
    return r;
}
__device__ __forceinline__ float2 unpack2(unsigned long long v) {
    float2 f;
    asm("mov.b64 {%0, %1}, %2;" : "=f"(f.x), "=f"(f.y) : "l"(v));
    return f;
}

// ---------------- SGEMM: C[M,N] = act(A[M,K] @ W[N,K]^T + bias) (+= if doacc) ----------------
// 128x128 tile, BK=8, 256 threads, 8x8 microtile, f32x2 packed FMAs, double-buffered SMEM.
__global__ __launch_bounds__(256, 2) void gemm128(
        const float* __restrict__ Ap, const float* __restrict__ Wp,
        const float* __restrict__ bias, float* __restrict__ Cp,
        int M, int N, int K, int dogelu, int doacc) {
    __shared__ __align__(16) float As[2][8][136];
    __shared__ __align__(16) float Bs[2][8][136];
    const int bm = blockIdx.y * 128, bn = blockIdx.x * 128;
    const int tid = threadIdx.x;
    const int tx = tid & 15, ty = tid >> 4;

    unsigned long long acc[8][4];
    #pragma unroll
    for (int i = 0; i < 8; i++)
        #pragma unroll
        for (int j = 0; j < 4; j++) acc[i][j] = 0ull;

    const int lrow = tid >> 1;
    const int lk = (tid & 1) * 4;
    const float* Ag = Ap + (size_t)(bm + lrow) * K + lk;
    const float* Wg = Wp + (size_t)(bn + lrow) * K + lk;

    // prologue: stage 0
    float4 a4 = *(const float4*)(Ag);
    float4 b4 = *(const float4*)(Wg);
    As[0][lk + 0][lrow] = a4.x; As[0][lk + 1][lrow] = a4.y;
    As[0][lk + 2][lrow] = a4.z; As[0][lk + 3][lrow] = a4.w;
    Bs[0][lk + 0][lrow] = b4.x; Bs[0][lk + 1][lrow] = b4.y;
    Bs[0][lk + 2][lrow] = b4.z; Bs[0][lk + 3][lrow] = b4.w;
    __syncthreads();

    const int niter = K >> 3;
    for (int it = 0; it < niter; it++) {
        const int cur = it & 1;
        if (it + 1 < niter) {
            a4 = *(const float4*)(Ag + (it + 1) * 8);
            b4 = *(const float4*)(Wg + (it + 1) * 8);
        }
        #pragma unroll
        for (int kk = 0; kk < 8; kk++) {
            const float* arow = &As[cur][kk][ty * 8];
            const float* brow = &Bs[cur][kk][tx * 8];
            ulonglong2 b01 = *(const ulonglong2*)(brow);
            ulonglong2 b23 = *(const ulonglong2*)(brow + 4);
            float4 al = *(const float4*)(arow);
            float4 ah = *(const float4*)(arow + 4);
            float av[8] = {al.x, al.y, al.z, al.w, ah.x, ah.y, ah.z, ah.w};
            #pragma unroll
            for (int i = 0; i < 8; i++) {
                unsigned long long ap = pack2(av[i]);
                fma2(acc[i][0], ap, b01.x);
                fma2(acc[i][1], ap, b01.y);
                fma2(acc[i][2], ap, b23.x);
                fma2(acc[i][3], ap, b23.y);
            }
        }
        if (it + 1 < niter) {
            const int nxt = (it + 1) & 1;
            As[nxt][lk + 0][lrow] = a4.x; As[nxt][lk + 1][lrow] = a4.y;
            As[nxt][lk + 2][lrow] = a4.z; As[nxt][lk + 3][lrow] = a4.w;
            Bs[nxt][lk + 0][lrow] = b4.x; Bs[nxt][lk + 1][lrow] = b4.y;
            Bs[nxt][lk + 2][lrow] = b4.z; Bs[nxt][lk + 3][lrow] = b4.w;
            __syncthreads();
        }
    }

    #pragma unroll
    for (int i = 0; i < 8; i++) {
        int m = bm + ty * 8 + i;
        float* crow = Cp + (size_t)m * N + bn + tx * 8;
        #pragma unroll
        for (int jj = 0; jj < 2; jj++) {
            float2 f0 = unpack2(acc[i][jj * 2 + 0]);
            float2 f1 = unpack2(acc[i][jj * 2 + 1]);
            float4 v = make_float4(f0.x, f0.y, f1.x, f1.y);
            if (bias) {
                float4 bb4 = *(const float4*)(bias + bn + tx * 8 + jj * 4);
                v.x += bb4.x; v.y += bb4.y; v.z += bb4.z; v.w += bb4.w;
            }
            if (dogelu) {
                v.x = 0.5f * v.x * (1.0f + erff(v.x * 0.70710678118654752f));
                v.y = 0.5f * v.y * (1.0f + erff(v.y * 0.70710678118654752f));
                v.z = 0.5f * v.z * (1.0f + erff(v.z * 0.70710678118654752f));
                v.w = 0.5f * v.w * (1.0f + erff(v.w * 0.70710678118654752f));
            }
            if (doacc) {
                float4 o4 = *(const float4*)(crow + jj * 4);
                v.x += o4.x; v.y += o4.y; v.z += o4.z; v.w += o4.w;
            }
            *(float4*)(crow + jj * 4) = v;
        }
    }
}

// ---------------- RoPE (in place on q,k sections of g_qkv) ----------------
__global__ void rope_kernel() {
    int idx = blockIdx.x * blockDim.x + threadIdx.x;   // BS * 2 * NH * 8
    int j   = idx & 7;
    int h   = (idx >> 3) & 7;
    int sec = (idx >> 6) & 1;     // 0 = q, 1 = k
    int row = idx >> 7;           // 0..BS-1
    int pos = row & (S - 1);
    float inv = powf(10000.0f, -(float)j * 0.125f);    // 10000^(-2j/ROT)
    float ang = (float)pos * inv;
    float c = cosf(ang), sn = sinf(ang);
    float* base = g_qkv + (size_t)row * 1536 + sec * 512 + h * 64;
    float x1 = base[j], x2 = base[j + 8];
    base[j]     = x1 * c - x2 * sn;
    base[j + 8] = x2 * c + x1 * sn;
}

// ---------------- scores + softmax + strict-causal renorm (block per (b,h,i) row) ----------
// Writes w~[i][s] = exp(score_s - mx) / (Z_{s<i} + 1e-8 * Z_{s<=i})  for s < i.
__global__ void scores_kernel() {
    int i = blockIdx.x, h = blockIdx.y, b = blockIdx.z;
    __shared__ float sc[S];
    __shared__ float qv[HD];
    __shared__ float redm[4], rz[4], rzs[4];
    int tid = threadIdx.x;          // 128
    int lane = tid & 31, wid = tid >> 5;

    const float* qrow = g_qkv + (size_t)(b * S + i) * 1536 + h * 64;
    if (tid < 64) qv[tid] = qrow[tid];
    __syncthreads();

    float mx = -1e30f;
    for (int s = wid; s <= i; s += 4) {
        const float* krow = g_qkv + (size_t)(b * S + s) * 1536 + 512 + h * 64;
        float d = qv[lane] * krow[lane] + qv[lane + 32] * krow[lane + 32];
        #pragma unroll
        for (int o = 16; o; o >>= 1) d += __shfl_xor_sync(0xffffffffu, d, o);
        d *= ATT_SCALE;
        if (lane == 0) sc[s] = d;
        mx = fmaxf(mx, d);
    }
    if (lane == 0) redm[wid] = mx;
    __syncthreads();
    mx = fmaxf(fmaxf(redm[0], redm[1]), fmaxf(redm[2], redm[3]));

    float z = 0.f, zs = 0.f;
    for (int s = tid; s <= i; s += 128) {
        float e = expf(sc[s] - mx);
        sc[s] = e;
        z += e;
        if (s < i) zs += e;
    }
    #pragma unroll
    for (int o = 16; o; o >>= 1) {
        z  += __shfl_xor_sync(0xffffffffu, z,  o);
        zs += __shfl_xor_sync(0xffffffffu, zs, o);
    }
    if (lane == 0) { rz[wid] = z; rzs[wid] = zs; }
    __syncthreads();
    z  = rz[0]  + rz[1]  + rz[2]  + rz[3];
    zs = rzs[0] + rzs[1] + rzs[2] + rzs[3];

    float invd = 1.0f / (zs + 1e-8f * z);
    float* wrow = g_w + ((size_t)(b * NH + h) * S + i) * S;
    for (int s = tid; s < i; s += 128) wrow[s] = sc[s] * invd;
}

// ---------------- scalar KA scan: c_0 = 1, c_i = sum_{s<i} w~[i][s] c_s ----------------
// One block per (b,h). 256 threads = 4 groups x 64 threads; 4 rows per super-step,
// cross-terms within the 4-row window resolved serially by thread 0.
__global__ void cscan_kernel() {
    int bh = blockIdx.x;
    const float* wbase = g_w + (size_t)bh * S * S;
    __shared__ float c_sh[S];
    __shared__ float red[8];
    __shared__ float crossw[4][4];
    int tid = threadIdx.x;        // 256
    int g = tid >> 6;             // group 0..3 (handles row i0+g)
    int gt = tid & 63;
    int lane = tid & 31;

    if (tid == 0) c_sh[0] = 1.0f;
    __syncthreads();

    for (int i0 = 1; i0 < S; i0 += 4) {
        int i = i0 + g;
        // cross weights w[i0+a][i0+b] for b<a
        if (tid < 16) {
            int a = tid >> 2, bb = tid & 3;
            if (bb < a && i0 + a < S)
                crossw[a][bb] = wbase[(size_t)(i0 + a) * S + (i0 + bb)];
        }
        float part = 0.f;
        if (i < S) {
            const float* wrow = wbase + (size_t)i * S;
            for (int s = gt; s < i0; s += 64)
                part += wrow[s] * c_sh[s];
        }
        #pragma unroll
        for (int o = 16; o; o >>= 1) part += __shfl_xor_sync(0xffffffffu, part, o);
        if (lane == 0) red[tid >> 5] = part;
        __syncthreads();
        if (tid == 0) {
            float c0 = red[0] + red[1];
            float c1 = red[2] + red[3];
            float c2 = red[4] + red[5];
            float c3 = red[6] + red[7];
            c1 += crossw[1][0] * c0;
            c2 += crossw[2][0] * c0 + crossw[2][1] * c1;
            c3 += crossw[3][0] * c0 + crossw[3][1] * c1 + crossw[3][2] * c2;
            c_sh[i0] = c0;
            if (i0 + 1 < S) c_sh[i0 + 1] = c1;
            if (i0 + 2 < S) c_sh[i0 + 2] = c2;
            if (i0 + 3 < S) c_sh[i0 + 3] = c3;
        }
        __syncthreads();
    }
    for (int s = tid; s < S; s += 256) g_c[bh * S + s] = c_sh[s];
}

// ---------------- attention output: A_i = c_i * v_0 (outer product) ----------------
__global__ void outer_kernel() {
    int idx = blockIdx.x * blockDim.x + threadIdx.x;   // BS*H = 2^20
    int d = idx & 63;
    int h = (idx >> 6) & 7;
    int s = (idx >> 9) & (S - 1);
    int b = idx >> 19;
    float v0 = g_qkv[(size_t)(b * S) * 1536 + 1024 + h * 64 + d];
    g_attn[idx] = g_c[(b * NH + h) * S + s] * v0;
}

// ---------------- launcher ----------------
extern "C" void kernel_launch(void* const* d_in, const int* in_sizes, int n_in,
                              void* d_out, int out_size) {
    const int*   ids     = (const int*)d_in[0];
    const float* embed   = (const float*)d_in[1];
    const float* qkv_w   = (const float*)d_in[2];
    const float* qkv_b   = (const float*)d_in[3];
    const float* dense_w = (const float*)d_in[4];
    const float* dense_b = (const float*)d_in[5];
    const float* fc1_w   = (const float*)d_in[6];
    const float* fc1_b   = (const float*)d_in[7];
    const float* fc2_w   = (const float*)d_in[8];
    const float* fc2_b   = (const float*)d_in[9];
    const float* ln_g    = (const float*)d_in[10];
    const float* ln_b    = (const float*)d_in[11];
    const float* fln_g   = (const float*)d_in[12];
    const float* fln_b   = (const float*)d_in[13];
    const float* out_w   = (const float*)d_in[14];
    float* out = (float*)d_out;

    float *h, *x, *qkv, *attn, *ff;
    cudaGetSymbolAddress((void**)&h,    g_h);
    cudaGetSymbolAddress((void**)&x,    g_x);
    cudaGetSymbolAddress((void**)&qkv,  g_qkv);
    cudaGetSymbolAddress((void**)&attn, g_attn);
    cudaGetSymbolAddress((void**)&ff,   g_ff);

    embed_kernel<<<(BS * H) / 256, 256>>>(ids, embed);

    for (int l = 0; l < NLAYER; l++) {
        ln_kernel<<<BS, 128>>>(h, x, ln_g + l * H, ln_b + l * H);

        // qkv: (2048x512) @ (1536x512)^T + b
        gemm128<<<dim3(1536 / 128, BS / 128), 256>>>(
            x, qkv_w + (size_t)l * 3 * H * H, qkv_b + (size_t)l * 3 * H,
            qkv, BS, 3 * H, H, 0, 0);

        rope_kernel<<<(BS * 2 * NH * 8) / 256, 256>>>();

        scores_kernel<<<dim3(S, NH, BATCH), 128>>>();

        cscan_kernel<<<BATCH * NH, 256>>>();

        outer_kernel<<<(BS * H) / 256, 256>>>();

        // dense: attn @ dense_w^T + b, accumulated into residual h
        gemm128<<<dim3(H / 128, BS / 128), 256>>>(
            attn, dense_w + (size_t)l * H * H, dense_b + (size_t)l * H,
            h, BS, H, H, 0, 1);

        // fc1 with exact GELU
        gemm128<<<dim3(FF / 128, BS / 128), 256>>>(
            x, fc1_w + (size_t)l * FF * H, fc1_b + (size_t)l * FF,
            ff, BS, FF, H, 1, 0);

        // fc2 accumulated into residual h
        gemm128<<<dim3(H / 128, BS / 128), 256>>>(
            ff, fc2_w + (size_t)l * H * FF, fc2_b + (size_t)l * H,
            h, BS, H, FF, 0, 1);
    }

    ln_kernel<<<BS, 128>>>(h, x, fln_g, fln_b);

    // logits: (2048x512) @ (50304x512)^T
    gemm128<<<dim3(VOCAB / 128, BS / 128), 256>>>(
        x, out_w, nullptr, out, BS, VOCAB, H, 0, 0);
}